// round 6
// baseline (speedup 1.0000x reference)
#include <cuda_runtime.h>

// Problem constants (shapes fixed by the dataset)
#define BB   64
#define KK   8
#define VV   128000
#define NS   25            // chunks per batch row
#define TPB  256
#define LCH  (VV / NS)     // 5120 elements per chunk
#define PER_T (LCH / TPB)  // 20 elements per thread (5 x float4)
#define FULL 0xFFFFFFFFu

// Scratch (device globals — zero-initialized; g_done self-resets every call)
__device__ float g_tsum[(long)BB * NS * TPB];
__device__ float g_chunksum[BB * NS];
__device__ int   g_done[BB];

// ---------------------------------------------------------------------------
// Single fused kernel: acceptance (redundant per block, L2-hot) + streaming
// partial sums + last-block hierarchical CDF search.
// __launch_bounds__(TPB, 4): 64-reg budget so all 10 float4 streaming loads
// stay simultaneously in flight (MLP=10/thread) instead of being serialized
// into a 36-reg load/use chain (the round-5 latency bottleneck).
// ---------------------------------------------------------------------------
__global__ void __launch_bounds__(TPB, 4)
k_fused(const int*   __restrict__ dtok,
        const float* __restrict__ dp,
        const float* __restrict__ op,
        const float* __restrict__ unif,
        const float* __restrict__ su,
        float*       __restrict__ out)
{
    int blk = blockIdx.x;
    int b = blk / NS, s = blk % NS;
    int t = threadIdx.x;
    int lane = t & 31, wid = t >> 5;

    // ---- acceptance (warp 0), broadcast via shared ----
    __shared__ int sh_na;
    if (wid == 0) {
        bool acc = false;
        if (lane < KK) {
            int tok  = dtok[b * KK + lane];
            float pd = dp[((long)b * KK + lane) * VV + tok];
            float po = op[((long)b * (KK + 1) + lane) * VV + tok];
            acc = unif[b * KK + lane] < fminf(1.0f, po / pd);
        }
        unsigned bits = __ballot_sync(FULL, acc) & ((1u << KK) - 1u);
        if (lane == 0) sh_na = __ffs(~bits) - 1;   // 8 if all accepted
    }
    __syncthreads();
    int na     = sh_na;
    int allacc = (na == KK) ? 1 : 0;
    int r      = min(na, KK - 1);

    // ---- streaming loads: issue ALL 10 float4 loads up front ----
    long off   = (long)s * LCH + (long)t * PER_T;
    long obase = ((long)b * (KK + 1) + (allacc ? KK : r)) * VV + off;
    long dbase = ((long)b * KK + r) * VV + off;
    const float4* o4p = (const float4*)(op + obase);
    const float4* d4p = (const float4*)(dp + dbase);

    float sum;
    if (allacc) {
        float4 o0 = o4p[0], o1 = o4p[1], o2 = o4p[2], o3 = o4p[3], o4v = o4p[4];
        sum = o0.x; sum += o0.y; sum += o0.z; sum += o0.w;
        sum += o1.x; sum += o1.y; sum += o1.z; sum += o1.w;
        sum += o2.x; sum += o2.y; sum += o2.z; sum += o2.w;
        sum += o3.x; sum += o3.y; sum += o3.z; sum += o3.w;
        sum += o4v.x; sum += o4v.y; sum += o4v.z; sum += o4v.w;
    } else {
        float4 o0 = o4p[0], o1 = o4p[1], o2 = o4p[2], o3 = o4p[3], o4v = o4p[4];
        float4 d0 = d4p[0], d1 = d4p[1], d2 = d4p[2], d3 = d4p[3], d4v = d4p[4];
        sum  = fmaxf(o0.x - d0.x, 0.0f); sum += fmaxf(o0.y - d0.y, 0.0f);
        sum += fmaxf(o0.z - d0.z, 0.0f); sum += fmaxf(o0.w - d0.w, 0.0f);
        sum += fmaxf(o1.x - d1.x, 0.0f); sum += fmaxf(o1.y - d1.y, 0.0f);
        sum += fmaxf(o1.z - d1.z, 0.0f); sum += fmaxf(o1.w - d1.w, 0.0f);
        sum += fmaxf(o2.x - d2.x, 0.0f); sum += fmaxf(o2.y - d2.y, 0.0f);
        sum += fmaxf(o2.z - d2.z, 0.0f); sum += fmaxf(o2.w - d2.w, 0.0f);
        sum += fmaxf(o3.x - d3.x, 0.0f); sum += fmaxf(o3.y - d3.y, 0.0f);
        sum += fmaxf(o3.z - d3.z, 0.0f); sum += fmaxf(o3.w - d3.w, 0.0f);
        sum += fmaxf(o4v.x - d4v.x, 0.0f); sum += fmaxf(o4v.y - d4v.y, 0.0f);
        sum += fmaxf(o4v.z - d4v.z, 0.0f); sum += fmaxf(o4v.w - d4v.w, 0.0f);
    }
    g_tsum[(long)blk * TPB + t] = sum;

    // ---- token scaffolding: block s==0 writes every slot except position na ----
    if (s == 0) {
        if (t <= KK && t != na)
            out[b * (KK + 1) + t] = (t < na) ? (float)dtok[b * KK + t] : -1.0f;
        if (t == 0)
            out[BB * (KK + 1) + b] = (float)na;    // num_accepted block
    }

    // ---- chunk sum ----
    float w = sum;
#pragma unroll
    for (int o = 16; o > 0; o >>= 1)
        w += __shfl_down_sync(FULL, w, o);
    __shared__ float sred[TPB / 32];
    if (lane == 0) sred[wid] = w;
    __syncthreads();
    if (t == 0) {
        float x = 0.0f;
#pragma unroll
        for (int j = 0; j < TPB / 32; ++j) x += sred[j];
        g_chunksum[blk] = x;
    }

    // ---- publish + elect last block of this batch ----
    __shared__ int sh_last;
    __syncthreads();                 // all g_tsum/g_chunksum writes issued
    if (t == 0) {
        __threadfence();             // make them device-visible
        int old = atomicAdd(&g_done[b], 1);
        sh_last = (old == NS - 1);
    }
    __syncthreads();
    if (!sh_last) return;
    if (t == 0) g_done[b] = 0;       // self-reset for next call / graph replay
    if (wid != 0) return;

    __threadfence();                 // acquire side before cross-block reads

    // ---- hierarchical CDF search (warp 0 of last block) ----
    // level 1: 25 chunk sums
    float cs = (lane < NS) ? __ldcg(&g_chunksum[b * NS + lane]) : 0.0f;
    float x = cs;
#pragma unroll
    for (int o = 1; o < 32; o <<= 1) {
        float y = __shfl_up_sync(FULL, x, o);
        if (lane >= o) x += y;
    }
    float tot = __shfl_sync(FULL, x, NS - 1);
    float T = allacc ? su[b] : su[b] * tot;

    unsigned bal = __ballot_sync(FULL, (lane < NS) && (x >= T));
    int token;
    if (bal == 0) {
        token = VV - 1;                              // u beyond total mass
    } else {
        int sc = __ffs(bal) - 1;                     // chunk with the crossing
        float base = __shfl_sync(FULL, x, sc) - __shfl_sync(FULL, cs, sc);

        // level 2: 256 thread sums in chunk sc, 32 at a time
        const float* ts = &g_tsum[(long)(b * NS + sc) * TPB];
        int   t_found = -1;
        float base_t  = 0.0f;
        float running = base;
#pragma unroll
        for (int g = 0; g < TPB / 32; ++g) {
            float v = __ldcg(&ts[g * 32 + lane]);
            float xx = v;
#pragma unroll
            for (int o = 1; o < 32; o <<= 1) {
                float y = __shfl_up_sync(FULL, xx, o);
                if (lane >= o) xx += y;
            }
            unsigned bb2 = __ballot_sync(FULL, running + xx >= T);
            if (bb2) {
                int l = __ffs(bb2) - 1;
                t_found = g * 32 + l;
                base_t  = running + __shfl_sync(FULL, xx, l)
                                  - __shfl_sync(FULL, v, l);
                break;
            }
            running += __shfl_sync(FULL, xx, 31);
        }

        if (t_found < 0) {
            token = min(sc * LCH + LCH, VV - 1);     // ulp-tie fallback
        } else {
            // level 3: 20 elements of thread t_found, same add order as pass
            long off0  = (long)sc * LCH + (long)t_found * PER_T;
            long obase2 = ((long)b * (KK + 1) + (allacc ? KK : r)) * VV + off0;
            long dbase2 = ((long)b * KK + r) * VV + off0;
            float val = 0.0f;
            if (lane < PER_T) {
                float o = op[obase2 + lane];
                val = allacc ? o : fmaxf(o - dp[dbase2 + lane], 0.0f);
            }
            float run = base_t;
            int found = PER_T;                       // fallback: end of span
#pragma unroll
            for (int i = 0; i < PER_T; ++i) {
                float v = __shfl_sync(FULL, val, i);
                run += v;
                if (found == PER_T && run >= T) found = i;
            }
            token = min((int)(off0 + found), VV - 1);
        }
    }

    if (lane == 0)
        out[b * (KK + 1) + na] = (float)token;
}

// ---------------------------------------------------------------------------
// Host launcher: classify inputs by element count (order-agnostic).
// ---------------------------------------------------------------------------
extern "C" void kernel_launch(void* const* d_in, const int* in_sizes, int n_in,
                              void* d_out, int out_size)
{
    const int*   dtok = nullptr;
    const float* dp   = nullptr;
    const float* op   = nullptr;
    const float* unif = nullptr;
    const float* su   = nullptr;

    int n512 = 0;
    for (int i = 0; i < n_in; ++i) {
        long sz = (long)in_sizes[i];
        if (sz == (long)BB * KK * VV)            dp = (const float*)d_in[i];
        else if (sz == (long)BB * (KK + 1) * VV) op = (const float*)d_in[i];
        else if (sz == BB)                       su = (const float*)d_in[i];
        else if (sz == BB * KK) {
            // relative order: draft_tokens, oracle_tokens, uniforms
            if      (n512 == 0) dtok = (const int*)d_in[i];
            else if (n512 == 2) unif = (const float*)d_in[i];
            ++n512;
        }
    }

    float* out = (float*)d_out;  // [tokens (B*(K+1)) | num_accepted (B)] as f32

    k_fused<<<BB * NS, TPB>>>(dtok, dp, op, unif, su, out);
}

// round 7
// speedup vs baseline: 1.4138x; 1.4138x over previous
#include <cuda_runtime.h>

// Problem constants (shapes fixed by the dataset)
#define BB   64
#define KK   8
#define VV   128000
#define NS   25              // chunks per batch row
#define TPB  256
#define LCH  (VV / NS)       // 5120 floats per chunk
#define NW   (TPB / 32)      // 8 warps per block
#define SEG  128             // floats per segment (one warp-wide float4 iter)
#define SPW  5               // segments per warp (5*128 = 640 floats)
#define SEGS (NW * SPW)      // 40 segments per chunk
#define FULL 0xFFFFFFFFu

// Scratch (device globals — zero-initialized; g_done self-resets every call)
__device__ float g_ssum[(long)BB * NS * SEGS];   // per-segment sums (256 KB)
__device__ float g_chunksum[BB * NS];
__device__ int   g_done[BB];

// ---------------------------------------------------------------------------
// Single fused kernel, fully-coalesced streaming:
//   * per-WARP acceptance (no block barrier on the load-issue critical path)
//   * warp-wide float4 iterations: each LDG.128 covers 512 contiguous bytes
//     (4 cache lines) instead of the 20-32 lines of the per-thread-contiguous
//     layout that capped round 5/6 at ~2.7 TB/s of L1 wavefront throughput.
//   * search hierarchy: 25 chunk sums -> 40 segment sums -> 128-float segment
// ---------------------------------------------------------------------------
__global__ void __launch_bounds__(TPB, 4)
k_fused(const int*   __restrict__ dtok,
        const float* __restrict__ dp,
        const float* __restrict__ op,
        const float* __restrict__ unif,
        const float* __restrict__ su,
        float*       __restrict__ out)
{
    int blk = blockIdx.x;
    int b = blk / NS, s = blk % NS;
    int t = threadIdx.x, lane = t & 31, wid = t >> 5;

    // ---- acceptance, computed redundantly per warp (L2/L1-hot) ----
    bool acc = false;
    if (lane < KK) {
        int tok  = dtok[b * KK + lane];
        float pd = dp[((long)b * KK + lane) * VV + tok];
        float po = op[((long)b * (KK + 1) + lane) * VV + tok];
        acc = unif[b * KK + lane] < fminf(1.0f, po / pd);
    }
    unsigned bits = __ballot_sync(FULL, acc) & ((1u << KK) - 1u);
    int na     = __ffs(~bits) - 1;          // 8 if all accepted
    int allacc = (na == KK) ? 1 : 0;
    int r      = min(na, KK - 1);

    // ---- coalesced streaming: warp covers 640 contiguous floats ----
    long row_off = (long)s * LCH + wid * (SPW * SEG);
    long obase   = ((long)b * (KK + 1) + (allacc ? KK : r)) * VV + row_off;
    long dbase   = ((long)b * KK + r) * VV + row_off;
    const float4* o4 = (const float4*)(op + obase);
    const float4* d4 = (const float4*)(dp + dbase);

    float p0, p1, p2, p3, p4;               // per-lane sums, one per segment
    if (allacc) {
        float4 a0 = o4[lane],      a1 = o4[32 + lane], a2 = o4[64 + lane];
        float4 a3 = o4[96 + lane], a4 = o4[128 + lane];
        p0 = a0.x + a0.y + a0.z + a0.w;
        p1 = a1.x + a1.y + a1.z + a1.w;
        p2 = a2.x + a2.y + a2.z + a2.w;
        p3 = a3.x + a3.y + a3.z + a3.w;
        p4 = a4.x + a4.y + a4.z + a4.w;
    } else {
        float4 a0 = o4[lane],      a1 = o4[32 + lane], a2 = o4[64 + lane];
        float4 a3 = o4[96 + lane], a4 = o4[128 + lane];
        float4 e0 = d4[lane],      e1 = d4[32 + lane], e2 = d4[64 + lane];
        float4 e3 = d4[96 + lane], e4 = d4[128 + lane];
        p0 = fmaxf(a0.x - e0.x, 0.f) + fmaxf(a0.y - e0.y, 0.f)
           + fmaxf(a0.z - e0.z, 0.f) + fmaxf(a0.w - e0.w, 0.f);
        p1 = fmaxf(a1.x - e1.x, 0.f) + fmaxf(a1.y - e1.y, 0.f)
           + fmaxf(a1.z - e1.z, 0.f) + fmaxf(a1.w - e1.w, 0.f);
        p2 = fmaxf(a2.x - e2.x, 0.f) + fmaxf(a2.y - e2.y, 0.f)
           + fmaxf(a2.z - e2.z, 0.f) + fmaxf(a2.w - e2.w, 0.f);
        p3 = fmaxf(a3.x - e3.x, 0.f) + fmaxf(a3.y - e3.y, 0.f)
           + fmaxf(a3.z - e3.z, 0.f) + fmaxf(a3.w - e3.w, 0.f);
        p4 = fmaxf(a4.x - e4.x, 0.f) + fmaxf(a4.y - e4.y, 0.f)
           + fmaxf(a4.z - e4.z, 0.f) + fmaxf(a4.w - e4.w, 0.f);
    }

    // ---- segment sums: warp tree-reduce each iteration ----
    __shared__ float ssh[SEGS];
    float q[SPW] = {p0, p1, p2, p3, p4};
#pragma unroll
    for (int i = 0; i < SPW; ++i) {
        float w = q[i];
#pragma unroll
        for (int o = 16; o > 0; o >>= 1)
            w += __shfl_down_sync(FULL, w, o);
        if (lane == 0) {
            ssh[wid * SPW + i] = w;
            g_ssum[(long)blk * SEGS + wid * SPW + i] = w;
        }
    }

    // ---- token scaffolding (block s==0 writes all slots except na) ----
    if (s == 0) {
        if (t <= KK && t != na)
            out[b * (KK + 1) + t] = (t < na) ? (float)dtok[b * KK + t] : -1.0f;
        if (t == 0)
            out[BB * (KK + 1) + b] = (float)na;
    }

    __syncthreads();
    if (t == 0) {
        float c = 0.0f;                      // sequential over segments:
#pragma unroll                               // consistent with level-2 search
        for (int j = 0; j < SEGS; ++j) c += ssh[j];
        g_chunksum[blk] = c;
    }

    // ---- publish + elect last block of this batch ----
    __shared__ int sh_last;
    __syncthreads();
    if (t == 0) {
        __threadfence();
        int old = atomicAdd(&g_done[b], 1);
        sh_last = (old == NS - 1);
    }
    __syncthreads();
    if (!sh_last) return;
    if (t == 0) g_done[b] = 0;               // self-reset for graph replay
    if (wid != 0) return;

    __threadfence();                          // acquire before cross-block reads

    // ---- level 1: 25 chunk sums ----
    float cs = (lane < NS) ? __ldcg(&g_chunksum[b * NS + lane]) : 0.0f;
    float x = cs;
#pragma unroll
    for (int o = 1; o < 32; o <<= 1) {
        float y = __shfl_up_sync(FULL, x, o);
        if (lane >= o) x += y;
    }
    float tot = __shfl_sync(FULL, x, NS - 1);
    float T = allacc ? su[b] : su[b] * tot;

    unsigned bal = __ballot_sync(FULL, (lane < NS) && (x >= T));
    int token;
    if (bal == 0) {
        token = VV - 1;
    } else {
        int sc = __ffs(bal) - 1;
        float base = __shfl_sync(FULL, x, sc) - __shfl_sync(FULL, cs, sc);

        // ---- level 2: 40 segment sums in chunk sc ----
        const float* ss = &g_ssum[(long)(b * NS + sc) * SEGS];
        int   j_found = -1;
        float base_t  = 0.0f;
        float running = base;
#pragma unroll
        for (int g = 0; g < 2; ++g) {
            int j = g * 32 + lane;
            float v = (j < SEGS) ? __ldcg(&ss[j]) : 0.0f;
            float xx = v;
#pragma unroll
            for (int o = 1; o < 32; o <<= 1) {
                float y = __shfl_up_sync(FULL, xx, o);
                if (lane >= o) xx += y;
            }
            unsigned bb2 = __ballot_sync(FULL, (j < SEGS) && (running + xx >= T));
            if (bb2) {
                int l = __ffs(bb2) - 1;
                j_found = g * 32 + l;
                base_t  = running + __shfl_sync(FULL, xx, l)
                                  - __shfl_sync(FULL, v, l);
                break;
            }
            running += __shfl_sync(FULL, xx, 31);
        }

        if (j_found < 0) {
            token = min(sc * LCH + LCH, VV - 1);     // ulp-tie fallback
        } else {
            // ---- level 3: one 128-float segment, coalesced re-read ----
            long off0 = (long)sc * LCH + (long)j_found * SEG;
            long ob2  = ((long)b * (KK + 1) + (allacc ? KK : r)) * VV + off0;
            long db2  = ((long)b * KK + r) * VV + off0;
            float4 ov = ((const float4*)(op + ob2))[lane];
            float v0, v1, v2, v3;
            if (allacc) {
                v0 = ov.x; v1 = ov.y; v2 = ov.z; v3 = ov.w;
            } else {
                float4 dv = ((const float4*)(dp + db2))[lane];
                v0 = fmaxf(ov.x - dv.x, 0.f); v1 = fmaxf(ov.y - dv.y, 0.f);
                v2 = fmaxf(ov.z - dv.z, 0.f); v3 = fmaxf(ov.w - dv.w, 0.f);
            }
            float local = v0 + v1 + v2 + v3;
            float xx = local;
#pragma unroll
            for (int o = 1; o < 32; o <<= 1) {
                float y = __shfl_up_sync(FULL, xx, o);
                if (lane >= o) xx += y;
            }
            unsigned bb3 = __ballot_sync(FULL, base_t + xx >= T);
            if (!bb3) {
                token = min((int)(off0 + SEG), VV - 1);   // ulp-tie fallback
            } else {
                int l = __ffs(bb3) - 1;
                float excl = base_t + __shfl_sync(FULL, xx, l)
                                    - __shfl_sync(FULL, local, l);
                float a0 = __shfl_sync(FULL, v0, l);
                float a1 = __shfl_sync(FULL, v1, l);
                float a2 = __shfl_sync(FULL, v2, l);
                float a3 = __shfl_sync(FULL, v3, l);
                (void)a3;
                float run = excl;
                int idx = 3;
                run += a0;
                if (run >= T) idx = 0;
                else { run += a1;
                    if (run >= T) idx = 1;
                    else { run += a2; if (run >= T) idx = 2; }
                }
                token = min((int)(off0 + l * 4 + idx), VV - 1);
            }
        }
    }

    if (lane == 0)
        out[b * (KK + 1) + na] = (float)token;
}

// ---------------------------------------------------------------------------
// Host launcher: classify inputs by element count (order-agnostic).
// ---------------------------------------------------------------------------
extern "C" void kernel_launch(void* const* d_in, const int* in_sizes, int n_in,
                              void* d_out, int out_size)
{
    const int*   dtok = nullptr;
    const float* dp   = nullptr;
    const float* op   = nullptr;
    const float* unif = nullptr;
    const float* su   = nullptr;

    int n512 = 0;
    for (int i = 0; i < n_in; ++i) {
        long sz = (long)in_sizes[i];
        if (sz == (long)BB * KK * VV)            dp = (const float*)d_in[i];
        else if (sz == (long)BB * (KK + 1) * VV) op = (const float*)d_in[i];
        else if (sz == BB)                       su = (const float*)d_in[i];
        else if (sz == BB * KK) {
            // relative order: draft_tokens, oracle_tokens, uniforms
            if      (n512 == 0) dtok = (const int*)d_in[i];
            else if (n512 == 2) unif = (const float*)d_in[i];
            ++n512;
        }
    }

    float* out = (float*)d_out;  // [tokens (B*(K+1)) | num_accepted (B)] as f32

    k_fused<<<BB * NS, TPB>>>(dtok, dp, op, unif, su, out);
}